// round 6
// baseline (speedup 1.0000x reference)
#include <cuda_runtime.h>
#include <math.h>

#define MAXN 100000
#define MAXE 800000

// Scratch (no allocation allowed in kernel_launch).
// Invariant: g_deg and g_sum are all-zero at kernel_launch entry.
//  - first call: __device__ globals are zero-initialized at module load
//  - later calls: k_nodedeg re-zeros g_sum, k_div re-zeros g_deg (below)
__device__ float g_deg[MAXN];        // sum |val| per destination
__device__ float g_sum[MAXN];        // softmax denominator per destination
__device__ float g_feat[MAXN * 32];  // per-node [f@W1_top | f@W1_bot]

__device__ __forceinline__ float leaky(float v) {
    return fmaxf(v, 0.1f * v);       // branchless: FMUL + FMNMX
}

// ---------------------------------------------------------------------------
// Kernel 1 (fused, 3 block ranges):
//   [0, nodeBlocks)              : per-node projection g[n] = f[n] @ Wcat
//   [nodeBlocks, +degBlocks)     : deg[i] += |val[e]|
//   [.., +sumBlocks)             : g_sum[n] = 0   (restores invariant for k_edge)
// ---------------------------------------------------------------------------
__global__ void k_nodedeg(const float* __restrict__ f, const float* __restrict__ W1,
                          const int* __restrict__ ind, const float* __restrict__ val,
                          int N, int E, int nodeBlocks, int degBlocks) {
    __shared__ float sW[128 * 32];

    if (blockIdx.x >= nodeBlocks) {
        int b = blockIdx.x - nodeBlocks;
        if (b < degBlocks) {
            int e = b * blockDim.x + threadIdx.x;
            if (e < E) atomicAdd(&g_deg[ind[e]], fabsf(val[e]));
        } else {
            int n = (b - degBlocks) * blockDim.x + threadIdx.x;
            if (n < N) g_sum[n] = 0.f;
        }
        return;
    }

    // sW[(k>>2)*128 + c*4 + (k&3)] = Wcat[k][c],
    // Wcat[k][c] = (c<16) ? W1[k][c] : W1[128+k][c-16]
    for (int t = threadIdx.x; t < 128 * 32; t += blockDim.x) {
        int kq = t >> 7;
        int rem = t & 127;
        int c = rem >> 2;
        int kl = rem & 3;
        int k = kq * 4 + kl;
        sW[t] = (c < 16) ? W1[k * 16 + c] : W1[(128 + k) * 16 + (c - 16)];
    }
    __syncthreads();

    int warp = threadIdx.x >> 5;
    int lane = threadIdx.x & 31;
    int n0 = (blockIdx.x * (blockDim.x >> 5) + warp) * 4;
    if (n0 >= N) return;

    const float4* fr0 = (const float4*)(f + (size_t)n0 * 128);
    const float4* fr1 = (const float4*)(f + (size_t)min(n0 + 1, N - 1) * 128);
    const float4* fr2 = (const float4*)(f + (size_t)min(n0 + 2, N - 1) * 128);
    const float4* fr3 = (const float4*)(f + (size_t)min(n0 + 3, N - 1) * 128);

    // dual partial accumulators per node -> 8 independent FMA chains
    float a0 = 0.f, b0 = 0.f, a1 = 0.f, b1 = 0.f;
    float a2 = 0.f, b2 = 0.f, a3 = 0.f, b3 = 0.f;
    const float4* sW4 = (const float4*)sW;

#pragma unroll 8
    for (int kq = 0; kq < 32; kq++) {
        float4 w = sW4[kq * 32 + lane];   // W[4kq..4kq+3][lane], conflict-free
        float4 v0 = fr0[kq];
        float4 v1 = fr1[kq];
        float4 v2 = fr2[kq];
        float4 v3 = fr3[kq];
        a0 = fmaf(v0.x, w.x, a0); b0 = fmaf(v0.y, w.y, b0);
        a0 = fmaf(v0.z, w.z, a0); b0 = fmaf(v0.w, w.w, b0);
        a1 = fmaf(v1.x, w.x, a1); b1 = fmaf(v1.y, w.y, b1);
        a1 = fmaf(v1.z, w.z, a1); b1 = fmaf(v1.w, w.w, b1);
        a2 = fmaf(v2.x, w.x, a2); b2 = fmaf(v2.y, w.y, b2);
        a2 = fmaf(v2.z, w.z, a2); b2 = fmaf(v2.w, w.w, b2);
        a3 = fmaf(v3.x, w.x, a3); b3 = fmaf(v3.y, w.y, b3);
        a3 = fmaf(v3.z, w.z, a3); b3 = fmaf(v3.w, w.w, b3);
    }

    g_feat[(size_t)n0 * 32 + lane] = a0 + b0;
    if (n0 + 1 < N) g_feat[(size_t)(n0 + 1) * 32 + lane] = a1 + b1;
    if (n0 + 2 < N) g_feat[(size_t)(n0 + 2) * 32 + lane] = a2 + b2;
    if (n0 + 3 < N) g_feat[(size_t)(n0 + 3) * 32 + lane] = a3 + b3;
}

// ---------------------------------------------------------------------------
// Kernel 2 (fused edge MLP + exp + sum):
//   Phase A: stage edge indices to smem.
//   Phase B: cooperative gather — 8 lanes per edge fetch gi-top/gj-bot float4s.
//   Phase C: thread-per-edge MLP, column-at-a-time vs transposed W2
//            (uniform-broadcast weight LDS), plain FFMA with dual partial
//            chains. ex=__expf(logit) (softmax shift-invariant, logits O(+-6):
//            no max pass), out[e]=ex, atomicAdd sum[i].
// ---------------------------------------------------------------------------
__global__ void __launch_bounds__(256, 5) k_edge(
        const int* __restrict__ ind, const float* __restrict__ val,
        const float* __restrict__ b1, const float* __restrict__ W2,
        const float* __restrict__ b2, const float* __restrict__ Wc,
        const float* __restrict__ bc, float* __restrict__ out, int E) {
    __shared__ float sX[256 * 34];     // staged [gi_top(16) | gj_bot(16)] per edge
    __shared__ int   sI[256], sJ[256];
    __shared__ float sW2T[17 * 18];    // transposed: sW2T[c*18+r] = W2[r][c]
    __shared__ float sB1[16], sB2[17], sWc[17];
    __shared__ float sBc;

    int tid = threadIdx.x;
    for (int t = tid; t < 289; t += blockDim.x) {
        int r = t / 17, c = t % 17;
        sW2T[c * 18 + r] = W2[t];
    }
    if (tid < 16) sB1[tid] = b1[tid];
    if (tid >= 32 && tid < 49) sB2[tid - 32] = b2[tid - 32];
    if (tid >= 64 && tid < 81) sWc[tid - 64] = Wc[tid - 64];
    if (tid == 96) sBc = bc[0];

    // Phase A
    int e0 = blockIdx.x * 256;
    int e = e0 + tid;
    bool valid = (e < E);
    sI[tid] = valid ? ind[e] : 0;
    sJ[tid] = valid ? ind[E + e] : 0;
    __syncthreads();

    // Phase B: 2048 float4 gather tasks, 8 per edge
#pragma unroll
    for (int it = 0; it < 8; it++) {
        int t = tid + it * 256;
        int eL = t >> 3;
        int p = t & 7;                              // 0-3: gi row, 4-7: gj row
        int node = (p < 4) ? sI[eL] : sJ[eL];
        float4 v = ((const float4*)(g_feat + (size_t)node * 32))[p];
        float* dst = &sX[eL * 34 + p * 4];          // even offset -> 8B aligned
        ((float2*)dst)[0] = make_float2(v.x, v.y);
        ((float2*)dst)[1] = make_float2(v.z, v.w);
    }
    __syncthreads();

    if (!valid) return;

    int i = sI[tid];
    const float2* sx2 = (const float2*)(sX + tid * 34);

    // x = leaky(gi_top + gj_bot + b1); x[16] = |v|/deg[i]
    float xs[16];
#pragma unroll
    for (int q = 0; q < 8; q++) {
        float2 a = sx2[q];
        float2 b = sx2[8 + q];
        xs[2 * q]     = leaky(a.x + b.x + sB1[2 * q]);
        xs[2 * q + 1] = leaky(a.y + b.y + sB1[2 * q + 1]);
    }
    float x16 = __fdividef(fabsf(val[e]), g_deg[i]);

    // column-at-a-time second layer + collapse, dual partials everywhere
    float ev0 = sBc, ev1 = 0.f;
#pragma unroll
    for (int c = 0; c < 17; c++) {
        const float* wc = sW2T + c * 18;            // uniform broadcast rows
        float acc0 = sB2[c];
        float acc1 = x16 * wc[16];
#pragma unroll
        for (int r = 0; r < 16; r += 2) {
            acc0 = fmaf(xs[r],     wc[r],     acc0);
            acc1 = fmaf(xs[r + 1], wc[r + 1], acc1);
        }
        float yc = leaky(acc0 + acc1);
        if (c & 1) ev1 = fmaf(yc, sWc[c], ev1);
        else       ev0 = fmaf(yc, sWc[c], ev0);
    }

    float ex = __expf(ev0 + ev1);
    out[e] = ex;
    atomicAdd(&g_sum[i], ex);
}

// ---------------------------------------------------------------------------
// Kernel 3: out[e] /= sum[i]; extra blocks re-zero g_deg for the next replay
// (g_deg is not read anywhere in this kernel, so no ordering hazard).
// ---------------------------------------------------------------------------
__global__ void k_div(const int* __restrict__ ind, float* __restrict__ out,
                      int E, int edgeBlocks, int N) {
    if (blockIdx.x >= edgeBlocks) {
        int n = (blockIdx.x - edgeBlocks) * blockDim.x + threadIdx.x;
        if (n < N) g_deg[n] = 0.f;
        return;
    }
    int e = blockIdx.x * blockDim.x + threadIdx.x;
    if (e >= E) return;
    out[e] = __fdividef(out[e], g_sum[ind[e]]);
}

// ---------------------------------------------------------------------------
extern "C" void kernel_launch(void* const* d_in, const int* in_sizes, int n_in,
                              void* d_out, int out_size) {
    const int*   ind = (const int*)d_in[0];    // [2, E]
    const float* val = (const float*)d_in[1];  // [E]
    const float* f   = (const float*)d_in[2];  // [N, 128]
    const float* W1  = (const float*)d_in[4];  // [256, 16]
    const float* b1  = (const float*)d_in[5];  // [16]
    const float* W2  = (const float*)d_in[6];  // [17, 17]
    const float* b2  = (const float*)d_in[7];  // [17]
    const float* Wc  = (const float*)d_in[8];  // [17, 1]
    const float* bc  = (const float*)d_in[9];  // [1]
    float* out = (float*)d_out;

    int E = in_sizes[1];
    int N = in_sizes[2] / 128;

    int tb = 256;
    int gN = (N + tb - 1) / tb;          // node-count blocks (zeroing)
    int gE = (E + tb - 1) / tb;          // edge-count blocks
    int nodesPerBlock = (tb / 32) * 4;   // 4 nodes per warp
    int nodeBlocks = (N + nodesPerBlock - 1) / nodesPerBlock;

    k_nodedeg<<<nodeBlocks + gE + gN, tb>>>(f, W1, ind, val, N, E, nodeBlocks, gE);
    k_edge<<<gE, tb>>>(ind, val, b1, W2, b2, Wc, bc, out, E);
    k_div<<<gE + gN, tb>>>(ind, out, E, gE, N);
}

// round 7
// speedup vs baseline: 1.3073x; 1.3073x over previous
#include <cuda_runtime.h>
#include <math.h>

#define MAXN 100000
#define MAXE 800000

// Scratch (no allocation allowed in kernel_launch).
// Invariant: g_deg and g_sum are all-zero at kernel_launch entry.
//  - first call: __device__ globals are zero-initialized at module load
//  - later calls: k_nodedeg re-zeros g_sum, k_div re-zeros g_deg
__device__ float g_deg[MAXN];        // sum |val| per destination
__device__ float g_sum[MAXN];        // softmax denominator per destination
__device__ float g_feat[MAXN * 32];  // per-node [f@W1_top | f@W1_bot]

__device__ __forceinline__ float leaky(float v) {
    return fmaxf(v, 0.1f * v);       // branchless: FMUL + FMNMX
}

// ---------------------------------------------------------------------------
// Kernel 1 (fused, 3 block ranges):
//   [0, nodeBlocks)          : projection g[n] = f[n] @ Wcat, 64-node tiles
//   [nodeBlocks, +degBlocks) : deg[i] += |val[e]|
//   [.., +N blocks)          : g_sum[n] = 0 (restores invariant for k_edge)
//
// Projection: f tile staged to smem with fully-coalesced LDG (streams DRAM
// once at high MLP); compute reads f as broadcast LDS.128 (1 wavefront,
// 29-cyc latency) and W as one divergent LDS.128 per k-quad, amortized over
// 8 nodes per warp.
// ---------------------------------------------------------------------------
__global__ void __launch_bounds__(256) k_nodedeg(
        const float* __restrict__ f, const float* __restrict__ W1,
        const int* __restrict__ ind, const float* __restrict__ val,
        int N, int E, int nodeBlocks, int degBlocks) {
    __shared__ float sW[128 * 32];   // 16 KB
    __shared__ float sF[64 * 128];   // 32 KB: 64-node f tile

    if (blockIdx.x >= nodeBlocks) {
        int b = blockIdx.x - nodeBlocks;
        if (b < degBlocks) {
            int e = b * blockDim.x + threadIdx.x;
            if (e < E) atomicAdd(&g_deg[ind[e]], fabsf(val[e]));
        } else {
            int n = (b - degBlocks) * blockDim.x + threadIdx.x;
            if (n < N) g_sum[n] = 0.f;
        }
        return;
    }

    // sW[(k>>2)*128 + c*4 + (k&3)] = Wcat[k][c],
    // Wcat[k][c] = (c<16) ? W1[k][c] : W1[128+k][c-16]
    for (int t = threadIdx.x; t < 128 * 32; t += blockDim.x) {
        int kq = t >> 7;
        int rem = t & 127;
        int c = rem >> 2;
        int kl = rem & 3;
        int k = kq * 4 + kl;
        sW[t] = (c < 16) ? W1[k * 16 + c] : W1[(128 + k) * 16 + (c - 16)];
    }

    // Stage f tile: 64 rows x 128 floats = 2048 float4, 8 per thread.
    // Lanes of a warp cover one contiguous row (512 B) -> perfectly coalesced.
    int n0 = blockIdx.x * 64;
    float4* sF4w = (float4*)sF;
#pragma unroll
    for (int it = 0; it < 8; it++) {
        int idx = threadIdx.x + it * 256;     // 0..2047
        int row = idx >> 5;                   // 0..63
        int c4  = idx & 31;                   // 0..31
        int n = min(n0 + row, N - 1);
        sF4w[row * 32 + c4] = ((const float4*)(f + (size_t)n * 128))[c4];
    }
    __syncthreads();

    int warp = threadIdx.x >> 5;
    int lane = threadIdx.x & 31;
    int base = warp * 8;                      // local node row of this warp

    const float4* sW4 = (const float4*)sW;
    const float4* sF4 = (const float4*)sF;

    float2 acc[8];
#pragma unroll
    for (int q = 0; q < 8; q++) acc[q] = make_float2(0.f, 0.f);

#pragma unroll 8
    for (int kq = 0; kq < 32; kq++) {
        float4 w = sW4[kq * 32 + lane];       // divergent, conflict-free (4 wf)
#pragma unroll
        for (int q = 0; q < 8; q++) {
            float4 v = sF4[(base + q) * 32 + kq];  // warp-broadcast (1 wf)
            acc[q].x = fmaf(v.x, w.x, acc[q].x);
            acc[q].y = fmaf(v.y, w.y, acc[q].y);
            acc[q].x = fmaf(v.z, w.z, acc[q].x);
            acc[q].y = fmaf(v.w, w.w, acc[q].y);
        }
    }

#pragma unroll
    for (int q = 0; q < 8; q++) {
        int n = n0 + base + q;
        if (n < N) g_feat[(size_t)n * 32 + lane] = acc[q].x + acc[q].y;
    }
}

// ---------------------------------------------------------------------------
// Kernel 2 (fused edge MLP + exp + sum):
//   Phase A: stage edge indices to smem.
//   Phase B: cooperative gather — 8 lanes per edge fetch gi-top/gj-bot float4s.
//   Phase C: thread-per-edge MLP, column-at-a-time vs transposed W2
//            (uniform-broadcast weight LDS), dual partial FMA chains.
//            ex=__expf(logit) (softmax shift-invariant, logits O(+-6):
//            no max pass), out[e]=ex, atomicAdd sum[i].
// ---------------------------------------------------------------------------
__global__ void __launch_bounds__(256, 5) k_edge(
        const int* __restrict__ ind, const float* __restrict__ val,
        const float* __restrict__ b1, const float* __restrict__ W2,
        const float* __restrict__ b2, const float* __restrict__ Wc,
        const float* __restrict__ bc, float* __restrict__ out, int E) {
    __shared__ float sX[256 * 34];     // staged [gi_top(16) | gj_bot(16)] per edge
    __shared__ int   sI[256], sJ[256];
    __shared__ float sW2T[17 * 18];    // transposed: sW2T[c*18+r] = W2[r][c]
    __shared__ float sB1[16], sB2[17], sWc[17];
    __shared__ float sBc;

    int tid = threadIdx.x;
    for (int t = tid; t < 289; t += blockDim.x) {
        int r = t / 17, c = t % 17;
        sW2T[c * 18 + r] = W2[t];
    }
    if (tid < 16) sB1[tid] = b1[tid];
    if (tid >= 32 && tid < 49) sB2[tid - 32] = b2[tid - 32];
    if (tid >= 64 && tid < 81) sWc[tid - 64] = Wc[tid - 64];
    if (tid == 96) sBc = bc[0];

    // Phase A
    int e0 = blockIdx.x * 256;
    int e = e0 + tid;
    bool valid = (e < E);
    sI[tid] = valid ? ind[e] : 0;
    sJ[tid] = valid ? ind[E + e] : 0;
    __syncthreads();

    // Phase B: 2048 float4 gather tasks, 8 per edge
#pragma unroll
    for (int it = 0; it < 8; it++) {
        int t = tid + it * 256;
        int eL = t >> 3;
        int p = t & 7;                              // 0-3: gi row, 4-7: gj row
        int node = (p < 4) ? sI[eL] : sJ[eL];
        float4 v = ((const float4*)(g_feat + (size_t)node * 32))[p];
        float* dst = &sX[eL * 34 + p * 4];          // even offset -> 8B aligned
        ((float2*)dst)[0] = make_float2(v.x, v.y);
        ((float2*)dst)[1] = make_float2(v.z, v.w);
    }
    __syncthreads();

    if (!valid) return;

    int i = sI[tid];
    const float2* sx2 = (const float2*)(sX + tid * 34);

    // x = leaky(gi_top + gj_bot + b1); x[16] = |v|/deg[i]
    float xs[16];
#pragma unroll
    for (int q = 0; q < 8; q++) {
        float2 a = sx2[q];
        float2 b = sx2[8 + q];
        xs[2 * q]     = leaky(a.x + b.x + sB1[2 * q]);
        xs[2 * q + 1] = leaky(a.y + b.y + sB1[2 * q + 1]);
    }
    float x16 = __fdividef(fabsf(val[e]), g_deg[i]);

    // column-at-a-time second layer + collapse, dual partials everywhere
    float ev0 = sBc, ev1 = 0.f;
#pragma unroll
    for (int c = 0; c < 17; c++) {
        const float* wc = sW2T + c * 18;            // uniform broadcast rows
        float acc0 = sB2[c];
        float acc1 = x16 * wc[16];
#pragma unroll
        for (int r = 0; r < 16; r += 2) {
            acc0 = fmaf(xs[r],     wc[r],     acc0);
            acc1 = fmaf(xs[r + 1], wc[r + 1], acc1);
        }
        float yc = leaky(acc0 + acc1);
        if (c & 1) ev1 = fmaf(yc, sWc[c], ev1);
        else       ev0 = fmaf(yc, sWc[c], ev0);
    }

    float ex = __expf(ev0 + ev1);
    out[e] = ex;
    atomicAdd(&g_sum[i], ex);
}

// ---------------------------------------------------------------------------
// Kernel 3: out[e] /= sum[i]; extra blocks re-zero g_deg for the next replay
// (g_deg is not read anywhere in this kernel, so no ordering hazard).
// ---------------------------------------------------------------------------
__global__ void k_div(const int* __restrict__ ind, float* __restrict__ out,
                      int E, int edgeBlocks, int N) {
    if (blockIdx.x >= edgeBlocks) {
        int n = (blockIdx.x - edgeBlocks) * blockDim.x + threadIdx.x;
        if (n < N) g_deg[n] = 0.f;
        return;
    }
    int e = blockIdx.x * blockDim.x + threadIdx.x;
    if (e >= E) return;
    out[e] = __fdividef(out[e], g_sum[ind[e]]);
}

// ---------------------------------------------------------------------------
extern "C" void kernel_launch(void* const* d_in, const int* in_sizes, int n_in,
                              void* d_out, int out_size) {
    const int*   ind = (const int*)d_in[0];    // [2, E]
    const float* val = (const float*)d_in[1];  // [E]
    const float* f   = (const float*)d_in[2];  // [N, 128]
    const float* W1  = (const float*)d_in[4];  // [256, 16]
    const float* b1  = (const float*)d_in[5];  // [16]
    const float* W2  = (const float*)d_in[6];  // [17, 17]
    const float* b2  = (const float*)d_in[7];  // [17]
    const float* Wc  = (const float*)d_in[8];  // [17, 1]
    const float* bc  = (const float*)d_in[9];  // [1]
    float* out = (float*)d_out;

    int E = in_sizes[1];
    int N = in_sizes[2] / 128;

    int tb = 256;
    int gN = (N + tb - 1) / tb;          // node-count blocks (zeroing)
    int gE = (E + tb - 1) / tb;          // edge-count blocks
    int nodeBlocks = (N + 63) / 64;      // 64-node tiles

    k_nodedeg<<<nodeBlocks + gE + gN, tb>>>(f, W1, ind, val, N, E, nodeBlocks, gE);
    k_edge<<<gE, tb>>>(ind, val, b1, W2, b2, Wc, bc, out, E);
    k_div<<<gE + gN, tb>>>(ind, out, E, gE, N);
}

// round 8
// speedup vs baseline: 1.4072x; 1.0764x over previous
#include <cuda_runtime.h>
#include <math.h>

#define MAXN 100000
#define MAXE 800000

// Scratch (no allocation allowed in kernel_launch).
// Invariant: g_deg and g_sum are all-zero at kernel_launch entry.
//  - first call: __device__ globals are zero-initialized at module load
//  - later calls: k_nodedeg re-zeros g_sum, k_div re-zeros g_deg
__device__ float g_deg[MAXN];        // sum |val| per destination
__device__ float g_sum[MAXN];        // softmax denominator per destination
__device__ float g_feat[MAXN * 32];  // per-node [f@W1_top | f@W1_bot]

typedef unsigned long long u64;

__device__ __forceinline__ float leaky(float v) {
    return fmaxf(v, 0.1f * v);       // branchless: FMUL + FMNMX
}

// packed fp32x2 FMA: c += a * b per 32-bit lane. Operands stay in b64 regs
// end-to-end (no mov pack/unpack in the hot loop).
__device__ __forceinline__ void fma2(u64& c, u64 a, u64 b) {
    asm("fma.rn.f32x2 %0, %1, %2, %0;" : "+l"(c) : "l"(a), "l"(b));
}
__device__ __forceinline__ u64 pack2(float lo, float hi) {
    u64 r;
    asm("mov.b64 %0, {%1, %2};" : "=l"(r) : "f"(lo), "f"(hi));
    return r;
}
__device__ __forceinline__ float2 unpack2(u64 v) {
    float lo, hi;
    asm("mov.b64 {%0, %1}, %2;" : "=f"(lo), "=f"(hi) : "l"(v));
    return make_float2(lo, hi);
}

// ---------------------------------------------------------------------------
// Kernel 1 (fused, 3 block ranges):
//   [0, nodeBlocks)          : projection g[n] = f[n] @ Wcat, 64-node tiles
//   [nodeBlocks, +degBlocks) : deg[i] += |val[e]|
//   [.., +N blocks)          : g_sum[n] = 0 (restores invariant for k_edge)
//
// Projection: f tile staged to smem coalesced; compute reads f as broadcast
// LDS.128 and W as one divergent LDS.128 per k-quad amortized over 8 nodes
// per warp. All FMAs are packed fma.rn.f32x2 (halves FMA-pipe issue count).
// ---------------------------------------------------------------------------
__global__ void __launch_bounds__(256, 4) k_nodedeg(
        const float* __restrict__ f, const float* __restrict__ W1,
        const int* __restrict__ ind, const float* __restrict__ val,
        int N, int E, int nodeBlocks, int degBlocks) {
    __shared__ float sW[128 * 32];   // 16 KB
    __shared__ float sF[64 * 128];   // 32 KB: 64-node f tile

    if (blockIdx.x >= nodeBlocks) {
        int b = blockIdx.x - nodeBlocks;
        if (b < degBlocks) {
            int e = b * blockDim.x + threadIdx.x;
            if (e < E) atomicAdd(&g_deg[ind[e]], fabsf(val[e]));
        } else {
            int n = (b - degBlocks) * blockDim.x + threadIdx.x;
            if (n < N) g_sum[n] = 0.f;
        }
        return;
    }

    // sW[(k>>2)*128 + c*4 + (k&3)] = Wcat[k][c],
    // Wcat[k][c] = (c<16) ? W1[k][c] : W1[128+k][c-16]
    for (int t = threadIdx.x; t < 128 * 32; t += blockDim.x) {
        int kq = t >> 7;
        int rem = t & 127;
        int c = rem >> 2;
        int kl = rem & 3;
        int k = kq * 4 + kl;
        sW[t] = (c < 16) ? W1[k * 16 + c] : W1[(128 + k) * 16 + (c - 16)];
    }

    // Stage f tile: 64 rows x 128 floats = 2048 float4, 8 per thread.
    // Lanes of a warp cover one contiguous row (512 B) -> perfectly coalesced.
    int n0 = blockIdx.x * 64;
    float4* sF4w = (float4*)sF;
#pragma unroll
    for (int it = 0; it < 8; it++) {
        int idx = threadIdx.x + it * 256;     // 0..2047
        int row = idx >> 5;                   // 0..63
        int c4  = idx & 31;                   // 0..31
        int n = min(n0 + row, N - 1);
        sF4w[row * 32 + c4] = ((const float4*)(f + (size_t)n * 128))[c4];
    }
    __syncthreads();

    int warp = threadIdx.x >> 5;
    int lane = threadIdx.x & 31;
    int base = warp * 8;                      // local node row of this warp

    const ulonglong2* sWp = (const ulonglong2*)sW;   // LDS.128 -> 2 packed pairs
    const ulonglong2* sFp = (const ulonglong2*)sF;

    u64 acc[8];
#pragma unroll
    for (int q = 0; q < 8; q++) acc[q] = 0ull;

#pragma unroll 8
    for (int kq = 0; kq < 32; kq++) {
        ulonglong2 w = sWp[kq * 32 + lane];   // divergent, conflict-free
#pragma unroll
        for (int q = 0; q < 8; q++) {
            ulonglong2 v = sFp[(base + q) * 32 + kq];   // warp-broadcast
            fma2(acc[q], v.x, w.x);           // 8 independent 2-step chains
            fma2(acc[q], v.y, w.y);
        }
    }

#pragma unroll
    for (int q = 0; q < 8; q++) {
        int n = n0 + base + q;
        float2 r = unpack2(acc[q]);
        if (n < N) g_feat[(size_t)n * 32 + lane] = r.x + r.y;
    }
}

// ---------------------------------------------------------------------------
// Kernel 2 (fused edge MLP + exp + sum):
//   Phase A: stage edge indices to smem.
//   Phase B: cooperative gather — 8 lanes per edge fetch gi-top/gj-bot float4s.
//   Phase C: thread-per-edge MLP, column-at-a-time vs transposed W2 with
//            packed f32x2 FMAs (8 per column instead of 16). ex=__expf(logit)
//            (softmax shift-invariant, logits O(+-6): no max pass),
//            out[e]=ex, atomicAdd sum[i].
// ---------------------------------------------------------------------------
__global__ void __launch_bounds__(256, 5) k_edge(
        const int* __restrict__ ind, const float* __restrict__ val,
        const float* __restrict__ b1, const float* __restrict__ W2,
        const float* __restrict__ b2, const float* __restrict__ Wc,
        const float* __restrict__ bc, float* __restrict__ out, int E) {
    __shared__ float sX[256 * 34];     // staged [gi_top(16) | gj_bot(16)] per edge
    __shared__ int   sI[256], sJ[256];
    __shared__ float sW2T[17 * 18];    // transposed: sW2T[c*18+r] = W2[r][c]
    __shared__ float sB1[16], sB2[17], sWc[17];
    __shared__ float sBc;

    int tid = threadIdx.x;
    for (int t = tid; t < 289; t += blockDim.x) {
        int r = t / 17, c = t % 17;
        sW2T[c * 18 + r] = W2[t];
    }
    if (tid < 16) sB1[tid] = b1[tid];
    if (tid >= 32 && tid < 49) sB2[tid - 32] = b2[tid - 32];
    if (tid >= 64 && tid < 81) sWc[tid - 64] = Wc[tid - 64];
    if (tid == 96) sBc = bc[0];

    // Phase A
    int e0 = blockIdx.x * 256;
    int e = e0 + tid;
    bool valid = (e < E);
    sI[tid] = valid ? ind[e] : 0;
    sJ[tid] = valid ? ind[E + e] : 0;
    __syncthreads();

    // Phase B: 2048 float4 gather tasks, 8 per edge
#pragma unroll
    for (int it = 0; it < 8; it++) {
        int t = tid + it * 256;
        int eL = t >> 3;
        int p = t & 7;                              // 0-3: gi row, 4-7: gj row
        int node = (p < 4) ? sI[eL] : sJ[eL];
        float4 v = ((const float4*)(g_feat + (size_t)node * 32))[p];
        float* dst = &sX[eL * 34 + p * 4];          // even offset -> 8B aligned
        ((float2*)dst)[0] = make_float2(v.x, v.y);
        ((float2*)dst)[1] = make_float2(v.z, v.w);
    }
    __syncthreads();

    if (!valid) return;

    int i = sI[tid];
    const float2* sx2 = (const float2*)(sX + tid * 34);

    // x = leaky(gi_top + gj_bot + b1), packed into 8 b64 pairs; x16 = |v|/deg
    u64 xp[8];
#pragma unroll
    for (int q = 0; q < 8; q++) {
        float2 a = sx2[q];
        float2 b = sx2[8 + q];
        xp[q] = pack2(leaky(a.x + b.x + sB1[2 * q]),
                      leaky(a.y + b.y + sB1[2 * q + 1]));
    }
    float x16 = __fdividef(fabsf(val[e]), g_deg[i]);

    // column-at-a-time second layer + collapse; dual packed partial chains
    float ev0 = sBc, ev1 = 0.f;
#pragma unroll
    for (int c = 0; c < 17; c++) {
        const u64* wc = (const u64*)(sW2T + c * 18);  // uniform broadcast LDS.64
        u64 accA = 0ull, accB = 0ull;
#pragma unroll
        for (int p = 0; p < 8; p += 2) {
            fma2(accA, xp[p],     wc[p]);
            fma2(accB, xp[p + 1], wc[p + 1]);
        }
        float2 a = unpack2(accA);
        float2 b = unpack2(accB);
        float yc = leaky((a.x + a.y) + (b.x + b.y)
                         + fmaf(x16, sW2T[c * 18 + 16], sB2[c]));
        if (c & 1) ev1 = fmaf(yc, sWc[c], ev1);
        else       ev0 = fmaf(yc, sWc[c], ev0);
    }

    float ex = __expf(ev0 + ev1);
    out[e] = ex;
    atomicAdd(&g_sum[i], ex);
}

// ---------------------------------------------------------------------------
// Kernel 3: out[e] /= sum[i], 4 edges/thread with coalesced int4/float4 and
// batched gathers (MLP=4 instead of 1). Extra blocks re-zero g_deg for the
// next replay (g_deg is not read here, so no ordering hazard).
// ---------------------------------------------------------------------------
__global__ void k_div(const int* __restrict__ ind, float* __restrict__ out,
                      int E, int edgeBlocks, int N) {
    if (blockIdx.x >= edgeBlocks) {
        int n = (blockIdx.x - edgeBlocks) * blockDim.x + threadIdx.x;
        if (n < N) g_deg[n] = 0.f;
        return;
    }
    int base = (blockIdx.x * blockDim.x + threadIdx.x) * 4;
    if (base + 3 < E) {
        int4   i4 = *(const int4*)(ind + base);
        float4 o4 = *(const float4*)(out + base);
        float s0 = g_sum[i4.x], s1 = g_sum[i4.y];
        float s2 = g_sum[i4.z], s3 = g_sum[i4.w];
        o4.x = __fdividef(o4.x, s0);
        o4.y = __fdividef(o4.y, s1);
        o4.z = __fdividef(o4.z, s2);
        o4.w = __fdividef(o4.w, s3);
        *(float4*)(out + base) = o4;
    } else {
        for (int e = base; e < E; e++)
            out[e] = __fdividef(out[e], g_sum[ind[e]]);
    }
}

// ---------------------------------------------------------------------------
extern "C" void kernel_launch(void* const* d_in, const int* in_sizes, int n_in,
                              void* d_out, int out_size) {
    const int*   ind = (const int*)d_in[0];    // [2, E]
    const float* val = (const float*)d_in[1];  // [E]
    const float* f   = (const float*)d_in[2];  // [N, 128]
    const float* W1  = (const float*)d_in[4];  // [256, 16]
    const float* b1  = (const float*)d_in[5];  // [16]
    const float* W2  = (const float*)d_in[6];  // [17, 17]
    const float* b2  = (const float*)d_in[7];  // [17]
    const float* Wc  = (const float*)d_in[8];  // [17, 1]
    const float* bc  = (const float*)d_in[9];  // [1]
    float* out = (float*)d_out;

    int E = in_sizes[1];
    int N = in_sizes[2] / 128;

    int tb = 256;
    int gN = (N + tb - 1) / tb;          // node-count blocks (zeroing)
    int gE = (E + tb - 1) / tb;          // edge-count blocks
    int gE4 = (E + tb * 4 - 1) / (tb * 4);  // 4 edges per thread
    int nodeBlocks = (N + 63) / 64;      // 64-node tiles

    k_nodedeg<<<nodeBlocks + gE + gN, tb>>>(f, W1, ind, val, N, E, nodeBlocks, gE);
    k_edge<<<gE, tb>>>(ind, val, b1, W2, b2, Wc, bc, out, E);
    k_div<<<gE4 + gN, tb>>>(ind, out, E, gE4, N);
}